// round 3
// baseline (speedup 1.0000x reference)
#include <cuda_runtime.h>
#include <math.h>

#define T_SEQ 4096
#define C_EMB 768
#define NH    12
#define HD    64
#define TK    32

// Scratch (allocation-guard-safe __device__ globals)
__device__ __align__(128) float g_q[(size_t)NH * T_SEQ * HD];
__device__ __align__(128) float g_k[(size_t)NH * T_SEQ * HD];
__device__ __align__(128) float g_v[(size_t)NH * T_SEQ * HD];
__device__ __align__(128) float g_att[(size_t)T_SEQ * C_EMB];

// ---------------------------------------------------------------------------
// GEMM: C[t,o] = sum_c X[t,c] * W[o,c]   (X:[T,768] row-major, W:[768,768])
// mode 0: X := g_att, write out[T,768] (final projection)
// mode 1/2/3: X := Xin, write head-major g_q/g_k/g_v  [h][t][d]
// 64x64 tile, 256 threads, 4x4 per thread. Both operands stored TRANSPOSED
// in smem ([c][t] / [c][o]) so the inner loop is 2x LDS.128 + 16 FFMA.
// ---------------------------------------------------------------------------
__global__ __launch_bounds__(256) void gemm_xwT(const float* __restrict__ Xin,
                                                const float* __restrict__ W,
                                                float* __restrict__ out,
                                                int mode) {
    __shared__ float Xt[TK][68];   // [c][t]
    __shared__ float Wt[TK][68];   // [c][o]
    const float* X = (mode == 0) ? g_att : Xin;
    const int tid = threadIdx.x;
    const int tx = tid & 15, ty = tid >> 4;
    const int row0 = blockIdx.x * 64;
    const int col0 = blockIdx.y * 64;
    float acc[4][4] = {};

    for (int k0 = 0; k0 < C_EMB; k0 += TK) {
        // load 64 rows x 32 cols (512 float4s, 2 per thread), store transposed
#pragma unroll
        for (int it = 0; it < 2; it++) {
            int idx = tid + it * 256;
            int r  = idx >> 3;          // 0..63
            int c4 = (idx & 7) * 4;     // 0,4,...,28
            float4 a = *(const float4*)(X + (size_t)(row0 + r) * C_EMB + k0 + c4);
            float4 b = *(const float4*)(W + (size_t)(col0 + r) * C_EMB + k0 + c4);
            Xt[c4 + 0][r] = a.x; Xt[c4 + 1][r] = a.y;
            Xt[c4 + 2][r] = a.z; Xt[c4 + 3][r] = a.w;
            Wt[c4 + 0][r] = b.x; Wt[c4 + 1][r] = b.y;
            Wt[c4 + 2][r] = b.z; Wt[c4 + 3][r] = b.w;
        }
        __syncthreads();
#pragma unroll
        for (int kk = 0; kk < TK; kk++) {
            float4 av = *(const float4*)&Xt[kk][ty * 4];   // broadcast (ty only)
            float4 bv = *(const float4*)&Wt[kk][tx * 4];
            float avr[4] = {av.x, av.y, av.z, av.w};
            float bvr[4] = {bv.x, bv.y, bv.z, bv.w};
#pragma unroll
            for (int i = 0; i < 4; i++)
#pragma unroll
                for (int j = 0; j < 4; j++)
                    acc[i][j] = fmaf(avr[i], bvr[j], acc[i][j]);
        }
        __syncthreads();
    }

    if (mode == 0) {
#pragma unroll
        for (int i = 0; i < 4; i++)
#pragma unroll
            for (int j = 0; j < 4; j++)
                out[(size_t)(row0 + ty * 4 + i) * C_EMB + col0 + tx * 4 + j] = acc[i][j];
    } else {
        float* dst = (mode == 1) ? g_q : (mode == 2) ? g_k : g_v;
        const int h = blockIdx.y;   // col tile == head (HD == 64 == tile width)
#pragma unroll
        for (int i = 0; i < 4; i++)
#pragma unroll
            for (int j = 0; j < 4; j++)
                dst[((size_t)h * T_SEQ + row0 + ty * 4 + i) * HD + tx * 4 + j] = acc[i][j];
    }
}

// ---------------------------------------------------------------------------
// Flash attention, fp32, causal.  BLOCK_M = BLOCK_N = 64, D = 64.
// 256 threads, 4x4 micro-tile. All smem operand tiles transposed so the
// inner loops are 2x LDS.128 (one broadcast) + 16 FFMA.
// smem: Qt[64][68] ([d][q]) | Kt[64][68] ([d][k]) | Pt[64][68] ([k][q]) | Vs[64][64]
// ---------------------------------------------------------------------------
__global__ __launch_bounds__(256) void attn_kernel() {
    extern __shared__ float sm[];
    float* Qt = sm;                          // 64*68 = 4352
    float* Kt = sm + 4352;                   // 4352
    float* Pt = sm + 8704;                   // 4352
    float* Vs = sm + 13056;                  // 4096

    const int tid = threadIdx.x;
    const int tx = tid & 15, ty = tid >> 4;
    const int it = gridDim.x - 1 - blockIdx.x;   // heavy tiles launch first
    const int h  = blockIdx.y;
    const int q0 = it * 64;

    const float* Qg = g_q + (size_t)h * T_SEQ * HD;
    const float* Kg = g_k + (size_t)h * T_SEQ * HD;
    const float* Vg = g_v + (size_t)h * T_SEQ * HD;

    // Load Q tile transposed: Qt[d][qrow]
#pragma unroll
    for (int rep = 0; rep < 4; rep++) {
        int row = (tid >> 4) + rep * 16;
        int d   = (tid & 15) * 4;
        float4 qv = *(const float4*)(Qg + (size_t)(q0 + row) * HD + d);
        Qt[(d + 0) * 68 + row] = qv.x;
        Qt[(d + 1) * 68 + row] = qv.y;
        Qt[(d + 2) * 68 + row] = qv.z;
        Qt[(d + 3) * 68 + row] = qv.w;
    }

    float m[4], l[4], o[4][4];
#pragma unroll
    for (int i = 0; i < 4; i++) {
        m[i] = -INFINITY; l[i] = 0.f;
#pragma unroll
        for (int j = 0; j < 4; j++) o[i][j] = 0.f;
    }
    __syncthreads();

    for (int jt = 0; jt <= it; jt++) {
        const int k0 = jt * 64;
        // Load K transposed (Kt[d][krow]) and V ([s][d])
#pragma unroll
        for (int rep = 0; rep < 4; rep++) {
            int row = (tid >> 4) + rep * 16;
            int d   = (tid & 15) * 4;
            float4 kv = *(const float4*)(Kg + (size_t)(k0 + row) * HD + d);
            Kt[(d + 0) * 68 + row] = kv.x;
            Kt[(d + 1) * 68 + row] = kv.y;
            Kt[(d + 2) * 68 + row] = kv.z;
            Kt[(d + 3) * 68 + row] = kv.w;
            *(float4*)(Vs + row * 64 + d) =
                *(const float4*)(Vg + (size_t)(k0 + row) * HD + d);
        }
        __syncthreads();

        // S = Q @ K^T : s[i][j], rows q0+ty*4+i, cols k0+tx*4+j
        float s[4][4] = {};
#pragma unroll 16
        for (int kk = 0; kk < 64; kk++) {
            float4 qv = *(const float4*)&Qt[kk * 68 + ty * 4];   // broadcast
            float4 kv = *(const float4*)&Kt[kk * 68 + tx * 4];
            float qr[4] = {qv.x, qv.y, qv.z, qv.w};
            float kr[4] = {kv.x, kv.y, kv.z, kv.w};
#pragma unroll
            for (int i = 0; i < 4; i++)
#pragma unroll
                for (int j = 0; j < 4; j++)
                    s[i][j] = fmaf(qr[i], kr[j], s[i][j]);
        }

        const float scale = 0.125f;   // 1/sqrt(64)
#pragma unroll
        for (int i = 0; i < 4; i++)
#pragma unroll
            for (int j = 0; j < 4; j++) s[i][j] *= scale;
        if (jt == it) {
#pragma unroll
            for (int i = 0; i < 4; i++)
#pragma unroll
                for (int j = 0; j < 4; j++)
                    if (k0 + tx * 4 + j > q0 + ty * 4 + i) s[i][j] = -INFINITY;
        }

        // Online softmax (row groups of 16 lanes share ty)
#pragma unroll
        for (int i = 0; i < 4; i++) {
            float mt = fmaxf(fmaxf(s[i][0], s[i][1]), fmaxf(s[i][2], s[i][3]));
            mt = fmaxf(mt, __shfl_xor_sync(0xffffffffu, mt, 1));
            mt = fmaxf(mt, __shfl_xor_sync(0xffffffffu, mt, 2));
            mt = fmaxf(mt, __shfl_xor_sync(0xffffffffu, mt, 4));
            mt = fmaxf(mt, __shfl_xor_sync(0xffffffffu, mt, 8));
            float mn = fmaxf(m[i], mt);
            float corr = __expf(m[i] - mn);
            m[i] = mn;
            float rs = 0.f;
#pragma unroll
            for (int j = 0; j < 4; j++) {
                float p = __expf(s[i][j] - mn);
                Pt[(tx * 4 + j) * 68 + ty * 4 + i] = p;   // Pt[key][q]
                rs += p;
            }
            rs += __shfl_xor_sync(0xffffffffu, rs, 1);
            rs += __shfl_xor_sync(0xffffffffu, rs, 2);
            rs += __shfl_xor_sync(0xffffffffu, rs, 4);
            rs += __shfl_xor_sync(0xffffffffu, rs, 8);
            l[i] = l[i] * corr + rs;
#pragma unroll
            for (int j = 0; j < 4; j++) o[i][j] *= corr;
        }
        __syncthreads();   // Pt visible to all

        // O += P @ V
#pragma unroll 16
        for (int ss = 0; ss < 64; ss++) {
            float4 pv = *(const float4*)&Pt[ss * 68 + ty * 4];   // broadcast
            float4 vv = *(const float4*)(Vs + ss * 64 + tx * 4);
            float pr[4] = {pv.x, pv.y, pv.z, pv.w};
#pragma unroll
            for (int i = 0; i < 4; i++) {
                o[i][0] = fmaf(pr[i], vv.x, o[i][0]);
                o[i][1] = fmaf(pr[i], vv.y, o[i][1]);
                o[i][2] = fmaf(pr[i], vv.z, o[i][2]);
                o[i][3] = fmaf(pr[i], vv.w, o[i][3]);
            }
        }
        __syncthreads();   // done with Pt/Kt/Vs before next tile load
    }

    // Normalize and write to att buffer [T, 768] (head columns interleaved)
#pragma unroll
    for (int i = 0; i < 4; i++) {
        float inv = 1.f / l[i];
#pragma unroll
        for (int j = 0; j < 4; j++)
            g_att[(size_t)(q0 + ty * 4 + i) * C_EMB + h * HD + tx * 4 + j] =
                o[i][j] * inv;
    }
}

// ---------------------------------------------------------------------------
extern "C" void kernel_launch(void* const* d_in, const int* in_sizes, int n_in,
                              void* d_out, int out_size) {
    (void)in_sizes; (void)n_in; (void)out_size;
    const float* x  = (const float*)d_in[0];
    const float* wq = (const float*)d_in[1];
    const float* wk = (const float*)d_in[2];
    const float* wv = (const float*)d_in[3];
    const float* wo = (const float*)d_in[4];
    float* out = (float*)d_out;

    const int attn_smem = (4352 * 3 + 4096) * 4;   // 68608 B
    cudaFuncSetAttribute(attn_kernel,
                         cudaFuncAttributeMaxDynamicSharedMemorySize, attn_smem);

    dim3 gemm_grid(T_SEQ / 64, C_EMB / 64);   // 64 x 12
    gemm_xwT<<<gemm_grid, 256>>>(x, wq, nullptr, 1);
    gemm_xwT<<<gemm_grid, 256>>>(x, wk, nullptr, 2);
    gemm_xwT<<<gemm_grid, 256>>>(x, wv, nullptr, 3);

    dim3 attn_grid(T_SEQ / 64, NH);           // 64 x 12
    attn_kernel<<<attn_grid, 256, attn_smem>>>();

    gemm_xwT<<<gemm_grid, 256>>>(nullptr, wo, out, 0);
}

// round 5
// speedup vs baseline: 2.1368x; 2.1368x over previous
#include <cuda_runtime.h>
#include <cuda_bf16.h>
#include <math.h>
#include <stdint.h>

#define T_SEQ 4096
#define C_EMB 768
#define NH    12
#define HD    64

typedef __nv_bfloat16 bf16;
typedef __nv_bfloat162 bf162;

// ---------------------------------------------------------------------------
// Scratch (__device__ globals — allocation-guard-safe)
// ---------------------------------------------------------------------------
__device__ __align__(128) bf16 g_xhi[(size_t)T_SEQ * C_EMB];
__device__ __align__(128) bf16 g_xlo[(size_t)T_SEQ * C_EMB];
__device__ __align__(128) bf16 g_whi[4][(size_t)C_EMB * C_EMB];
__device__ __align__(128) bf16 g_wlo[4][(size_t)C_EMB * C_EMB];
__device__ __align__(128) bf16 g_qhi[(size_t)NH * T_SEQ * HD];
__device__ __align__(128) bf16 g_qlo[(size_t)NH * T_SEQ * HD];
__device__ __align__(128) bf16 g_khi[(size_t)NH * T_SEQ * HD];
__device__ __align__(128) bf16 g_klo[(size_t)NH * T_SEQ * HD];
__device__ __align__(128) bf16 g_vhi[(size_t)NH * T_SEQ * HD];
__device__ __align__(128) bf16 g_vlo[(size_t)NH * T_SEQ * HD];
__device__ __align__(128) bf16 g_ahi[(size_t)T_SEQ * C_EMB];
__device__ __align__(128) bf16 g_alo[(size_t)T_SEQ * C_EMB];

// ---------------------------------------------------------------------------
// Warp MMA helpers (baseline PTX — no 'a'-arch features)
// ---------------------------------------------------------------------------
__device__ __forceinline__ uint32_t smem_u32(const void* p) {
    uint32_t a;
    asm("{ .reg .u64 t; cvta.to.shared.u64 t, %1; cvt.u32.u64 %0, t; }"
        : "=r"(a) : "l"(p));
    return a;
}
__device__ __forceinline__ void ldm4(uint32_t addr, uint32_t* r) {
    asm volatile("ldmatrix.sync.aligned.m8n8.x4.shared.b16 {%0,%1,%2,%3}, [%4];"
                 : "=r"(r[0]), "=r"(r[1]), "=r"(r[2]), "=r"(r[3]) : "r"(addr));
}
__device__ __forceinline__ void mma16816(float* d, const uint32_t* a,
                                         const uint32_t* b) {
    asm volatile(
        "mma.sync.aligned.m16n8k16.row.col.f32.bf16.bf16.f32 "
        "{%0,%1,%2,%3}, {%4,%5,%6,%7}, {%8,%9}, {%0,%1,%2,%3};"
        : "+f"(d[0]), "+f"(d[1]), "+f"(d[2]), "+f"(d[3])
        : "r"(a[0]), "r"(a[1]), "r"(a[2]), "r"(a[3]), "r"(b[0]), "r"(b[1]));
}
// pack two fp32 into (hi, lo) bf16x2 words
__device__ __forceinline__ void hilo2(float v0, float v1, uint32_t& h, uint32_t& l) {
    bf162 hh, ll;
    hh.x = __float2bfloat16(v0); hh.y = __float2bfloat16(v1);
    ll.x = __float2bfloat16(v0 - __bfloat162float(hh.x));
    ll.y = __float2bfloat16(v1 - __bfloat162float(hh.y));
    h = *reinterpret_cast<uint32_t*>(&hh);
    l = *reinterpret_cast<uint32_t*>(&ll);
}

// ---------------------------------------------------------------------------
// fp32 -> bf16 (hi, lo) split
// ---------------------------------------------------------------------------
__global__ __launch_bounds__(256) void split_bf16(const float* __restrict__ src,
                                                  bf16* __restrict__ hi,
                                                  bf16* __restrict__ lo, int n4) {
    int i = blockIdx.x * 256 + threadIdx.x;
    if (i >= n4) return;
    float4 v = ((const float4*)src)[i];
    uint32_t h0, l0, h1, l1;
    hilo2(v.x, v.y, h0, l0);
    hilo2(v.z, v.w, h1, l1);
    ((uint32_t*)hi)[i * 2 + 0] = h0;
    ((uint32_t*)hi)[i * 2 + 1] = h1;
    ((uint32_t*)lo)[i * 2 + 0] = l0;
    ((uint32_t*)lo)[i * 2 + 1] = l1;
}

// ---------------------------------------------------------------------------
// Tensor GEMM: C[t,o] = sum_c X[t,c] * W[o,c], both operands split hi/lo.
// CTA 128x128, 8 warps (4m x 2n), k-chunk 64, smem row stride 72 bf16.
// outf != 0 : write fp32 [T,768]. else: write bf16 hi/lo head-major [h][t][d].
// ---------------------------------------------------------------------------
#define GS 72
#define GAH 0
#define GAL 18432
#define GBH 36864
#define GBL 55296
#define GEMM_SMEM 73728

__global__ __launch_bounds__(256) void gemm_tc(
    const bf16* __restrict__ Ahi, const bf16* __restrict__ Alo,
    const bf16* __restrict__ Bhi, const bf16* __restrict__ Blo,
    float* __restrict__ outf, bf16* __restrict__ Dhi, bf16* __restrict__ Dlo) {
    extern __shared__ bf16 smg[];
    bf16* sAh = smg;
    bf16* sAl = smg + GAL / 2;
    bf16* sBh = smg + GBH / 2;
    bf16* sBl = smg + GBL / 2;
    const uint32_t sb = smem_u32(smg);
    const int tid = threadIdx.x, lane = tid & 31, wid = tid >> 5;
    const int wm = wid & 3, wn = wid >> 2;
    const int row0 = blockIdx.x * 128, col0 = blockIdx.y * 128;
    const int g = lane >> 3, lr = lane & 7;

    float acc[2][8][4];
#pragma unroll
    for (int i = 0; i < 2; i++)
#pragma unroll
        for (int j = 0; j < 8; j++)
#pragma unroll
            for (int c = 0; c < 4; c++) acc[i][j][c] = 0.f;

    for (int k0 = 0; k0 < C_EMB; k0 += 64) {
#pragma unroll
        for (int itr = 0; itr < 4; itr++) {
            int idx = tid + itr * 256;         // 0..1023
            int r = idx >> 3, q = idx & 7;
            size_t ga = (size_t)(row0 + r) * C_EMB + k0 + q * 8;
            size_t gb = (size_t)(col0 + r) * C_EMB + k0 + q * 8;
            *(uint4*)(sAh + r * GS + q * 8) = *(const uint4*)(Ahi + ga);
            *(uint4*)(sAl + r * GS + q * 8) = *(const uint4*)(Alo + ga);
            *(uint4*)(sBh + r * GS + q * 8) = *(const uint4*)(Bhi + gb);
            *(uint4*)(sBl + r * GS + q * 8) = *(const uint4*)(Blo + gb);
        }
        __syncthreads();
#pragma unroll
        for (int kt = 0; kt < 4; kt++) {
            uint32_t ah[2][4], al[2][4];
#pragma unroll
            for (int mt = 0; mt < 2; mt++) {
                int m0 = wm * 32 + mt * 16;
                uint32_t aoff = (uint32_t)(((m0 + lr + (g & 1) * 8) * GS +
                                            kt * 16 + (g >> 1) * 8) * 2);
                ldm4(sb + GAH + aoff, ah[mt]);
                ldm4(sb + GAL + aoff, al[mt]);
            }
#pragma unroll
            for (int np = 0; np < 4; np++) {
                int n0 = wn * 64 + np * 16;
                uint32_t boff = (uint32_t)(((n0 + lr + (g >> 1) * 8) * GS +
                                            kt * 16 + (g & 1) * 8) * 2);
                uint32_t bh[4], bl[4];
                ldm4(sb + GBH + boff, bh);
                ldm4(sb + GBL + boff, bl);
#pragma unroll
                for (int mt = 0; mt < 2; mt++) {
                    mma16816(acc[mt][2 * np],     ah[mt], &bh[0]);
                    mma16816(acc[mt][2 * np],     ah[mt], &bl[0]);
                    mma16816(acc[mt][2 * np],     al[mt], &bh[0]);
                    mma16816(acc[mt][2 * np + 1], ah[mt], &bh[2]);
                    mma16816(acc[mt][2 * np + 1], ah[mt], &bl[2]);
                    mma16816(acc[mt][2 * np + 1], al[mt], &bh[2]);
                }
            }
        }
        __syncthreads();
    }

    const int r = lane >> 2, cq = (lane & 3) * 2;
#pragma unroll
    for (int mt = 0; mt < 2; mt++) {
#pragma unroll
        for (int nt = 0; nt < 8; nt++) {
            int grow = row0 + wm * 32 + mt * 16 + r;
            int gc = col0 + wn * 64 + nt * 8 + cq;
            if (outf) {
                float2 v0 = make_float2(acc[mt][nt][0], acc[mt][nt][1]);
                float2 v1 = make_float2(acc[mt][nt][2], acc[mt][nt][3]);
                *(float2*)(outf + (size_t)grow * C_EMB + gc) = v0;
                *(float2*)(outf + (size_t)(grow + 8) * C_EMB + gc) = v1;
            } else {
                uint32_t h0, l0, h1, l1;
                hilo2(acc[mt][nt][0], acc[mt][nt][1], h0, l0);
                hilo2(acc[mt][nt][2], acc[mt][nt][3], h1, l1);
                int hh = gc >> 6, d = gc & 63;
                size_t b0 = ((size_t)hh * T_SEQ + grow) * HD + d;
                size_t b1 = ((size_t)hh * T_SEQ + grow + 8) * HD + d;
                *(uint32_t*)(Dhi + b0) = h0;
                *(uint32_t*)(Dlo + b0) = l0;
                *(uint32_t*)(Dhi + b1) = h1;
                *(uint32_t*)(Dlo + b1) = l1;
            }
        }
    }
}

// ---------------------------------------------------------------------------
// Tensor flash attention, causal. BLOCK_M=128 (8 warps x m16), BLOCK_N=64.
// Q/K smem [row][d] stride 72; V stored transposed [d][key] stride 72.
// S and PV via mma.sync bf16 with hi/lo split (3 products each).
// Writes bf16 hi/lo att [T, 768].
// ---------------------------------------------------------------------------
#define AS 72
#define AQH 0
#define AQL 18432
#define AKH 36864
#define AKL 46080
#define AVH 55296
#define AVL 64512
#define ATTN_SMEM 73728

__global__ __launch_bounds__(256) void attn_tc() {
    extern __shared__ bf16 sma[];
    bf16* sQh = sma;
    bf16* sQl = sma + AQL / 2;
    bf16* sKh = sma + AKH / 2;
    bf16* sKl = sma + AKL / 2;
    bf16* sVh = sma + AVH / 2;
    bf16* sVl = sma + AVL / 2;
    const uint32_t sb = smem_u32(sma);
    const int tid = threadIdx.x, lane = tid & 31, wid = tid >> 5;
    const int g = lane >> 3, lr = lane & 7;
    const int itc = gridDim.x - 1 - blockIdx.x;   // heavy first
    const int h = blockIdx.y;
    const int q0 = itc * 128;
    const int ntiles = 2 * itc + 2;               // KV tiles of 64

    const bf16* Qh = g_qhi + (size_t)h * T_SEQ * HD;
    const bf16* Ql = g_qlo + (size_t)h * T_SEQ * HD;
    const bf16* Kh = g_khi + (size_t)h * T_SEQ * HD;
    const bf16* Kl = g_klo + (size_t)h * T_SEQ * HD;
    const bf16* Vh = g_vhi + (size_t)h * T_SEQ * HD;
    const bf16* Vl = g_vlo + (size_t)h * T_SEQ * HD;

    // Q tile: 128 rows x 64
#pragma unroll
    for (int itr = 0; itr < 4; itr++) {
        int idx = tid + itr * 256;
        int r = idx >> 3, q = idx & 7;
        *(uint4*)(sQh + r * AS + q * 8) =
            *(const uint4*)(Qh + (size_t)(q0 + r) * HD + q * 8);
        *(uint4*)(sQl + r * AS + q * 8) =
            *(const uint4*)(Ql + (size_t)(q0 + r) * HD + q * 8);
    }
    __syncthreads();

    // preload Q fragments (loop-invariant)
    uint32_t qfh[4][4], qfl[4][4];
#pragma unroll
    for (int kt = 0; kt < 4; kt++) {
        uint32_t aoff = (uint32_t)(((wid * 16 + lr + (g & 1) * 8) * AS +
                                    kt * 16 + (g >> 1) * 8) * 2);
        ldm4(sb + AQH + aoff, qfh[kt]);
        ldm4(sb + AQL + aoff, qfl[kt]);
    }

    float m[2] = {-INFINITY, -INFINITY}, lsum[2] = {0.f, 0.f};
    float ov[8][4];
#pragma unroll
    for (int i = 0; i < 8; i++)
#pragma unroll
        for (int c = 0; c < 4; c++) ov[i][c] = 0.f;

    for (int jt = 0; jt < ntiles; jt++) {
        const int k0b = jt * 64;
        // K tiles (64x64)
#pragma unroll
        for (int itr = 0; itr < 2; itr++) {
            int idx = tid + itr * 256;
            int r = idx >> 3, q = idx & 7;
            *(uint4*)(sKh + r * AS + q * 8) =
                *(const uint4*)(Kh + (size_t)(k0b + r) * HD + q * 8);
            *(uint4*)(sKl + r * AS + q * 8) =
                *(const uint4*)(Kl + (size_t)(k0b + r) * HD + q * 8);
        }
        // V tiles transposed: sV[d][key]
#pragma unroll
        for (int itr = 0; itr < 2; itr++) {
            int idx = tid + itr * 256;
            int r = idx >> 3, q = idx & 7;
            uint4 vh4 = *(const uint4*)(Vh + (size_t)(k0b + r) * HD + q * 8);
            uint4 vl4 = *(const uint4*)(Vl + (size_t)(k0b + r) * HD + q * 8);
            const bf16* ph = (const bf16*)&vh4;
            const bf16* pl = (const bf16*)&vl4;
#pragma unroll
            for (int j = 0; j < 8; j++) {
                sVh[(q * 8 + j) * AS + r] = ph[j];
                sVl[(q * 8 + j) * AS + r] = pl[j];
            }
        }
        __syncthreads();

        // S = Q K^T  (warp: 16 rows x 64 keys)
        float sv[8][4];
#pragma unroll
        for (int i = 0; i < 8; i++)
#pragma unroll
            for (int c = 0; c < 4; c++) sv[i][c] = 0.f;
#pragma unroll
        for (int kt = 0; kt < 4; kt++) {
#pragma unroll
            for (int np = 0; np < 4; np++) {
                uint32_t boff = (uint32_t)(((np * 16 + lr + (g >> 1) * 8) * AS +
                                            kt * 16 + (g & 1) * 8) * 2);
                uint32_t bh[4], bl[4];
                ldm4(sb + AKH + boff, bh);
                ldm4(sb + AKL + boff, bl);
                mma16816(sv[2 * np],     qfh[kt], &bh[0]);
                mma16816(sv[2 * np],     qfh[kt], &bl[0]);
                mma16816(sv[2 * np],     qfl[kt], &bh[0]);
                mma16816(sv[2 * np + 1], qfh[kt], &bh[2]);
                mma16816(sv[2 * np + 1], qfh[kt], &bl[2]);
                mma16816(sv[2 * np + 1], qfl[kt], &bh[2]);
            }
        }

        // scale + causal mask
        const float scale = 0.125f;
        const int rbase = q0 + wid * 16 + (lane >> 2);
        const bool diag = (k0b + 63) > (q0 + wid * 16);
#pragma unroll
        for (int nt = 0; nt < 8; nt++) {
#pragma unroll
            for (int c = 0; c < 4; c++) {
                float s = sv[nt][c] * scale;
                if (diag) {
                    int row = rbase + ((c >> 1) << 3);
                    int col = k0b + nt * 8 + (lane & 3) * 2 + (c & 1);
                    if (col > row) s = -INFINITY;
                }
                sv[nt][c] = s;
            }
        }
        // online softmax (rows r and r+8)
#pragma unroll
        for (int half = 0; half < 2; half++) {
            int ci = half * 2;
            float mt = -INFINITY;
#pragma unroll
            for (int nt = 0; nt < 8; nt++)
                mt = fmaxf(mt, fmaxf(sv[nt][ci], sv[nt][ci + 1]));
            mt = fmaxf(mt, __shfl_xor_sync(0xffffffffu, mt, 1));
            mt = fmaxf(mt, __shfl_xor_sync(0xffffffffu, mt, 2));
            float mn = fmaxf(m[half], mt);
            float corr = __expf(m[half] - mn);
            m[half] = mn;
            float rs = 0.f;
#pragma unroll
            for (int nt = 0; nt < 8; nt++) {
                float p0 = __expf(sv[nt][ci] - mn);
                float p1 = __expf(sv[nt][ci + 1] - mn);
                sv[nt][ci] = p0; sv[nt][ci + 1] = p1;
                rs += p0 + p1;
            }
            rs += __shfl_xor_sync(0xffffffffu, rs, 1);
            rs += __shfl_xor_sync(0xffffffffu, rs, 2);
            lsum[half] = lsum[half] * corr + rs;
#pragma unroll
            for (int dn = 0; dn < 8; dn++) {
                ov[dn][ci] *= corr;
                ov[dn][ci + 1] *= corr;
            }
        }

        // O += P V  (P fragments built on the fly, hi/lo split)
#pragma unroll
        for (int kt = 0; kt < 4; kt++) {
            uint32_t pfh[4], pfl[4];
            hilo2(sv[2 * kt][0],     sv[2 * kt][1],     pfh[0], pfl[0]);
            hilo2(sv[2 * kt][2],     sv[2 * kt][3],     pfh[1], pfl[1]);
            hilo2(sv[2 * kt + 1][0], sv[2 * kt + 1][1], pfh[2], pfl[2]);
            hilo2(sv[2 * kt + 1][2], sv[2 * kt + 1][3], pfh[3], pfl[3]);
#pragma unroll
            for (int dp = 0; dp < 4; dp++) {
                uint32_t boff = (uint32_t)(((dp * 16 + lr + (g >> 1) * 8) * AS +
                                            kt * 16 + (g & 1) * 8) * 2);
                uint32_t vfh[4], vfl[4];
                ldm4(sb + AVH + boff, vfh);
                ldm4(sb + AVL + boff, vfl);
                mma16816(ov[2 * dp],     pfh, &vfh[0]);
                mma16816(ov[2 * dp],     pfh, &vfl[0]);
                mma16816(ov[2 * dp],     pfl, &vfh[0]);
                mma16816(ov[2 * dp + 1], pfh, &vfh[2]);
                mma16816(ov[2 * dp + 1], pfh, &vfl[2]);
                mma16816(ov[2 * dp + 1], pfl, &vfh[2]);
            }
        }
        __syncthreads();
    }

    // epilogue: normalize, split hi/lo, write att [T, 768]
    const int r = lane >> 2, cq = (lane & 3) * 2;
#pragma unroll
    for (int half = 0; half < 2; half++) {
        float inv = 1.f / lsum[half];
        int rg = q0 + wid * 16 + r + half * 8;
#pragma unroll
        for (int dn = 0; dn < 8; dn++) {
            float v0 = ov[dn][half * 2] * inv;
            float v1 = ov[dn][half * 2 + 1] * inv;
            uint32_t hh, ll;
            hilo2(v0, v1, hh, ll);
            size_t base = (size_t)rg * C_EMB + h * HD + dn * 8 + cq;
            *(uint32_t*)(g_ahi + base) = hh;
            *(uint32_t*)(g_alo + base) = ll;
        }
    }
}

// ---------------------------------------------------------------------------
extern "C" void kernel_launch(void* const* d_in, const int* in_sizes, int n_in,
                              void* d_out, int out_size) {
    (void)in_sizes; (void)n_in; (void)out_size;
    const float* x  = (const float*)d_in[0];
    const float* wq = (const float*)d_in[1];
    const float* wk = (const float*)d_in[2];
    const float* wv = (const float*)d_in[3];
    const float* wo = (const float*)d_in[4];
    float* out = (float*)d_out;

    bf16 *xhi, *xlo, *whi, *wlo, *qhi, *qlo, *khi, *klo, *vhi, *vlo, *ahi, *alo;
    cudaGetSymbolAddress((void**)&xhi, g_xhi);
    cudaGetSymbolAddress((void**)&xlo, g_xlo);
    cudaGetSymbolAddress((void**)&whi, g_whi);
    cudaGetSymbolAddress((void**)&wlo, g_wlo);
    cudaGetSymbolAddress((void**)&qhi, g_qhi);
    cudaGetSymbolAddress((void**)&qlo, g_qlo);
    cudaGetSymbolAddress((void**)&khi, g_khi);
    cudaGetSymbolAddress((void**)&klo, g_klo);
    cudaGetSymbolAddress((void**)&vhi, g_vhi);
    cudaGetSymbolAddress((void**)&vlo, g_vlo);
    cudaGetSymbolAddress((void**)&ahi, g_ahi);
    cudaGetSymbolAddress((void**)&alo, g_alo);
    cudaFuncSetAttribute(gemm_tc, cudaFuncAttributeMaxDynamicSharedMemorySize,
                         GEMM_SMEM);
    cudaFuncSetAttribute(attn_tc, cudaFuncAttributeMaxDynamicSharedMemorySize,
                         ATTN_SMEM);
    const size_t WSZ = (size_t)C_EMB * C_EMB;

    int nx4 = (T_SEQ * C_EMB) / 4;
    int nw4 = (C_EMB * C_EMB) / 4;
    split_bf16<<<(nx4 + 255) / 256, 256>>>(x, xhi, xlo, nx4);
    split_bf16<<<(nw4 + 255) / 256, 256>>>(wq, whi + 0 * WSZ, wlo + 0 * WSZ, nw4);
    split_bf16<<<(nw4 + 255) / 256, 256>>>(wk, whi + 1 * WSZ, wlo + 1 * WSZ, nw4);
    split_bf16<<<(nw4 + 255) / 256, 256>>>(wv, whi + 2 * WSZ, wlo + 2 * WSZ, nw4);
    split_bf16<<<(nw4 + 255) / 256, 256>>>(wo, whi + 3 * WSZ, wlo + 3 * WSZ, nw4);

    dim3 ggrid(T_SEQ / 128, C_EMB / 128);   // 32 x 6
    gemm_tc<<<ggrid, 256, GEMM_SMEM>>>(xhi, xlo, whi + 0 * WSZ, wlo + 0 * WSZ,
                                       nullptr, qhi, qlo);
    gemm_tc<<<ggrid, 256, GEMM_SMEM>>>(xhi, xlo, whi + 1 * WSZ, wlo + 1 * WSZ,
                                       nullptr, khi, klo);
    gemm_tc<<<ggrid, 256, GEMM_SMEM>>>(xhi, xlo, whi + 2 * WSZ, wlo + 2 * WSZ,
                                       nullptr, vhi, vlo);

    dim3 agrid(T_SEQ / 128, NH);            // 32 x 12
    attn_tc<<<agrid, 256, ATTN_SMEM>>>();

    gemm_tc<<<ggrid, 256, GEMM_SMEM>>>(ahi, alo, whi + 3 * WSZ, wlo + 3 * WSZ,
                                       out, nullptr, nullptr);
}

// round 6
// speedup vs baseline: 2.9206x; 1.3668x over previous
#include <cuda_runtime.h>
#include <cuda_bf16.h>
#include <math.h>
#include <stdint.h>

#define T_SEQ 4096
#define C_EMB 768
#define NH    12
#define HD    64
#define NW4   147456          // (768*768)/4

typedef __nv_bfloat16 bf16;
typedef __nv_bfloat162 bf162;

// ---------------------------------------------------------------------------
// Scratch (__device__ globals — allocation-guard-safe)
// ---------------------------------------------------------------------------
__device__ __align__(128) bf16 g_xhi[(size_t)T_SEQ * C_EMB];
__device__ __align__(128) bf16 g_xlo[(size_t)T_SEQ * C_EMB];
__device__ __align__(128) bf16 g_whi[4][(size_t)C_EMB * C_EMB];
__device__ __align__(128) bf16 g_wlo[4][(size_t)C_EMB * C_EMB];
__device__ __align__(128) bf16 g_qhi[(size_t)NH * T_SEQ * HD];
__device__ __align__(128) bf16 g_qlo[(size_t)NH * T_SEQ * HD];
__device__ __align__(128) bf16 g_khi[(size_t)NH * T_SEQ * HD];
__device__ __align__(128) bf16 g_klo[(size_t)NH * T_SEQ * HD];
__device__ __align__(128) bf16 g_vhi[(size_t)NH * T_SEQ * HD];
__device__ __align__(128) bf16 g_vlo[(size_t)NH * T_SEQ * HD];
__device__ __align__(128) bf16 g_ahi[(size_t)T_SEQ * C_EMB];
__device__ __align__(128) bf16 g_alo[(size_t)T_SEQ * C_EMB];

// ---------------------------------------------------------------------------
// Helpers (baseline PTX only — no 'a'-arch features)
// ---------------------------------------------------------------------------
__device__ __forceinline__ uint32_t smem_u32(const void* p) {
    uint32_t a;
    asm("{ .reg .u64 t; cvta.to.shared.u64 t, %1; cvt.u32.u64 %0, t; }"
        : "=r"(a) : "l"(p));
    return a;
}
__device__ __forceinline__ void ldm4(uint32_t addr, uint32_t* r) {
    asm volatile("ldmatrix.sync.aligned.m8n8.x4.shared.b16 {%0,%1,%2,%3}, [%4];"
                 : "=r"(r[0]), "=r"(r[1]), "=r"(r[2]), "=r"(r[3]) : "r"(addr));
}
__device__ __forceinline__ void ldm4t(uint32_t addr, uint32_t* r) {
    asm volatile("ldmatrix.sync.aligned.m8n8.x4.trans.shared.b16 {%0,%1,%2,%3}, [%4];"
                 : "=r"(r[0]), "=r"(r[1]), "=r"(r[2]), "=r"(r[3]) : "r"(addr));
}
__device__ __forceinline__ void mma16816(float* d, const uint32_t* a,
                                         const uint32_t* b) {
    asm volatile(
        "mma.sync.aligned.m16n8k16.row.col.f32.bf16.bf16.f32 "
        "{%0,%1,%2,%3}, {%4,%5,%6,%7}, {%8,%9}, {%0,%1,%2,%3};"
        : "+f"(d[0]), "+f"(d[1]), "+f"(d[2]), "+f"(d[3])
        : "r"(a[0]), "r"(a[1]), "r"(a[2]), "r"(a[3]), "r"(b[0]), "r"(b[1]));
}
__device__ __forceinline__ void hilo2(float v0, float v1, uint32_t& h, uint32_t& l) {
    bf162 hh, ll;
    hh.x = __float2bfloat16(v0); hh.y = __float2bfloat16(v1);
    ll.x = __float2bfloat16(v0 - __bfloat162float(hh.x));
    ll.y = __float2bfloat16(v1 - __bfloat162float(hh.y));
    h = *reinterpret_cast<uint32_t*>(&hh);
    l = *reinterpret_cast<uint32_t*>(&ll);
}
#define CP16(dst, src) \
    asm volatile("cp.async.cg.shared.global [%0], [%1], 16;" \
                 :: "r"(dst), "l"(src) : "memory")
#define CPCOMMIT() asm volatile("cp.async.commit_group;" ::: "memory")
#define CPWAIT0() asm volatile("cp.async.wait_group 0;" ::: "memory")
#define CPWAIT1() asm volatile("cp.async.wait_group 1;" ::: "memory")

// ---------------------------------------------------------------------------
// fp32 -> bf16 (hi, lo) splits
// ---------------------------------------------------------------------------
__global__ __launch_bounds__(256) void split_bf16(const float* __restrict__ src,
                                                  bf16* __restrict__ hi,
                                                  bf16* __restrict__ lo, int n4) {
    int i = blockIdx.x * 256 + threadIdx.x;
    if (i >= n4) return;
    float4 v = ((const float4*)src)[i];
    uint32_t h0, l0, h1, l1;
    hilo2(v.x, v.y, h0, l0);
    hilo2(v.z, v.w, h1, l1);
    ((uint32_t*)hi)[i * 2 + 0] = h0;
    ((uint32_t*)hi)[i * 2 + 1] = h1;
    ((uint32_t*)lo)[i * 2 + 0] = l0;
    ((uint32_t*)lo)[i * 2 + 1] = l1;
}

__global__ __launch_bounds__(256) void split_w4(const float* __restrict__ w0,
                                                const float* __restrict__ w1,
                                                const float* __restrict__ w2,
                                                const float* __restrict__ w3) {
    int i = blockIdx.x * 256 + threadIdx.x;
    if (i >= 4 * NW4) return;
    int m = i / NW4, j = i - m * NW4;
    const float* src = (m == 0) ? w0 : (m == 1) ? w1 : (m == 2) ? w2 : w3;
    float4 v = ((const float4*)src)[j];
    uint32_t h0, l0, h1, l1;
    hilo2(v.x, v.y, h0, l0);
    hilo2(v.z, v.w, h1, l1);
    uint32_t* hp = (uint32_t*)(g_whi[m]);
    uint32_t* lp = (uint32_t*)(g_wlo[m]);
    hp[j * 2 + 0] = h0; hp[j * 2 + 1] = h1;
    lp[j * 2 + 0] = l0; lp[j * 2 + 1] = l1;
}

// ---------------------------------------------------------------------------
// Tensor GEMM: C[t,o] = sum_c X[t,c] * W[o,c], hi/lo split operands.
// CTA 128x128, 8 warps (4m x 2n), k-chunk 64, smem stride 72 bf16.
// blockIdx.z selects weight matrix. outf != 0: write fp32; else bf16 hi/lo
// head-major g_q/g_k/g_v by z.
// ---------------------------------------------------------------------------
#define GS 72
#define GAH 0
#define GAL 18432
#define GBH 36864
#define GBL 55296
#define GEMM_SMEM 73728

__global__ __launch_bounds__(256) void gemm_tc(
    const bf16* __restrict__ Ahi, const bf16* __restrict__ Alo,
    const bf16* __restrict__ BhiB, const bf16* __restrict__ BloB,
    float* __restrict__ outf) {
    extern __shared__ bf16 smg[];
    const uint32_t sb = smem_u32(smg);
    const int tid = threadIdx.x, lane = tid & 31, wid = tid >> 5;
    const int wm = wid & 3, wn = wid >> 2;
    const int row0 = blockIdx.x * 128, col0 = blockIdx.y * 128;
    const int z = blockIdx.z;
    const bf16* Bhi = BhiB + (size_t)z * C_EMB * C_EMB;
    const bf16* Blo = BloB + (size_t)z * C_EMB * C_EMB;
    const int g = lane >> 3, lr = lane & 7;

    float acc[2][8][4];
#pragma unroll
    for (int i = 0; i < 2; i++)
#pragma unroll
        for (int j = 0; j < 8; j++)
#pragma unroll
            for (int c = 0; c < 4; c++) acc[i][j][c] = 0.f;

    for (int k0 = 0; k0 < C_EMB; k0 += 64) {
#pragma unroll
        for (int itr = 0; itr < 4; itr++) {
            int idx = tid + itr * 256;
            int r = idx >> 3, q = idx & 7;
            size_t ga = (size_t)(row0 + r) * C_EMB + k0 + q * 8;
            size_t gb = (size_t)(col0 + r) * C_EMB + k0 + q * 8;
            uint32_t so = (uint32_t)((r * GS + q * 8) * 2);
            CP16(sb + GAH + so, Ahi + ga);
            CP16(sb + GAL + so, Alo + ga);
            CP16(sb + GBH + so, Bhi + gb);
            CP16(sb + GBL + so, Blo + gb);
        }
        CPCOMMIT();
        CPWAIT0();
        __syncthreads();
#pragma unroll
        for (int kt = 0; kt < 4; kt++) {
            uint32_t ah[2][4], al[2][4];
#pragma unroll
            for (int mt = 0; mt < 2; mt++) {
                int m0 = wm * 32 + mt * 16;
                uint32_t aoff = (uint32_t)(((m0 + lr + (g & 1) * 8) * GS +
                                            kt * 16 + (g >> 1) * 8) * 2);
                ldm4(sb + GAH + aoff, ah[mt]);
                ldm4(sb + GAL + aoff, al[mt]);
            }
#pragma unroll
            for (int np = 0; np < 4; np++) {
                int n0 = wn * 64 + np * 16;
                uint32_t boff = (uint32_t)(((n0 + lr + (g >> 1) * 8) * GS +
                                            kt * 16 + (g & 1) * 8) * 2);
                uint32_t bh[4], bl[4];
                ldm4(sb + GBH + boff, bh);
                ldm4(sb + GBL + boff, bl);
#pragma unroll
                for (int mt = 0; mt < 2; mt++) {
                    mma16816(acc[mt][2 * np],     ah[mt], &bh[0]);
                    mma16816(acc[mt][2 * np],     ah[mt], &bl[0]);
                    mma16816(acc[mt][2 * np],     al[mt], &bh[0]);
                    mma16816(acc[mt][2 * np + 1], ah[mt], &bh[2]);
                    mma16816(acc[mt][2 * np + 1], ah[mt], &bl[2]);
                    mma16816(acc[mt][2 * np + 1], al[mt], &bh[2]);
                }
            }
        }
        __syncthreads();
    }

    const int r = lane >> 2, cq = (lane & 3) * 2;
    bf16* Dhi = (z == 0) ? g_qhi : (z == 1) ? g_khi : g_vhi;
    bf16* Dlo = (z == 0) ? g_qlo : (z == 1) ? g_klo : g_vlo;
#pragma unroll
    for (int mt = 0; mt < 2; mt++) {
#pragma unroll
        for (int nt = 0; nt < 8; nt++) {
            int grow = row0 + wm * 32 + mt * 16 + r;
            int gc = col0 + wn * 64 + nt * 8 + cq;
            if (outf) {
                *(float2*)(outf + (size_t)grow * C_EMB + gc) =
                    make_float2(acc[mt][nt][0], acc[mt][nt][1]);
                *(float2*)(outf + (size_t)(grow + 8) * C_EMB + gc) =
                    make_float2(acc[mt][nt][2], acc[mt][nt][3]);
            } else {
                uint32_t h0, l0, h1, l1;
                hilo2(acc[mt][nt][0], acc[mt][nt][1], h0, l0);
                hilo2(acc[mt][nt][2], acc[mt][nt][3], h1, l1);
                int hh = gc >> 6, d = gc & 63;
                size_t b0 = ((size_t)hh * T_SEQ + grow) * HD + d;
                size_t b1 = ((size_t)hh * T_SEQ + grow + 8) * HD + d;
                *(uint32_t*)(Dhi + b0) = h0;
                *(uint32_t*)(Dlo + b0) = l0;
                *(uint32_t*)(Dhi + b1) = h1;
                *(uint32_t*)(Dlo + b1) = l1;
            }
        }
    }
}

// ---------------------------------------------------------------------------
// Tensor flash attention, causal. BLOCK_M=128 (8 warps x m16), BLOCK_N=64.
// Double-buffered cp.async KV pipeline; stage 1 reuses the Q smem region.
// V row-major in smem, fragments via ldmatrix.trans.
// stage layout (bytes): KH=0 KL=9216 VH=18432 VL=27648  (stage = 36864)
// Q: QH=36864 QL=55296.  Total smem 73728 B.
// ---------------------------------------------------------------------------
#define AS  72
#define STG 36864
#define AVHO 18432
#define AVLO 27648
#define AQH 36864
#define AQL 55296
#define ATTN_SMEM 73728

__global__ __launch_bounds__(256) void attn_tc() {
    extern __shared__ char smc[];
    const uint32_t sb = smem_u32(smc);
    const int tid = threadIdx.x, lane = tid & 31, wid = tid >> 5;
    const int g = lane >> 3, lr = lane & 7;
    const int itc = gridDim.x - 1 - blockIdx.x;   // heavy first
    const int h = blockIdx.y;
    const int q0 = itc * 128;
    const int ntiles = 2 * itc + 2;               // KV tiles of 64

    const bf16* Qh = g_qhi + (size_t)h * T_SEQ * HD;
    const bf16* Ql = g_qlo + (size_t)h * T_SEQ * HD;
    const bf16* Kh = g_khi + (size_t)h * T_SEQ * HD;
    const bf16* Kl = g_klo + (size_t)h * T_SEQ * HD;
    const bf16* Vh = g_vhi + (size_t)h * T_SEQ * HD;
    const bf16* Vl = g_vlo + (size_t)h * T_SEQ * HD;

    // Q tile -> smem (region doubles as KV stage 1 afterwards)
#pragma unroll
    for (int itr = 0; itr < 4; itr++) {
        int idx = tid + itr * 256;
        int r = idx >> 3, q = idx & 7;
        uint32_t so = (uint32_t)((r * AS + q * 8) * 2);
        *(uint4*)(smc + AQH + so) = *(const uint4*)(Qh + (size_t)(q0 + r) * HD + q * 8);
        *(uint4*)(smc + AQL + so) = *(const uint4*)(Ql + (size_t)(q0 + r) * HD + q * 8);
    }
    __syncthreads();

    uint32_t qfh[4][4], qfl[4][4];
#pragma unroll
    for (int kt = 0; kt < 4; kt++) {
        uint32_t aoff = (uint32_t)(((wid * 16 + lr + (g & 1) * 8) * AS +
                                    kt * 16 + (g >> 1) * 8) * 2);
        ldm4(sb + AQH + aoff, qfh[kt]);
        ldm4(sb + AQL + aoff, qfl[kt]);
    }
    __syncthreads();   // all warps done with Q region before it becomes stage 1

    // prefetch helper (lambda): KV tile jt2 -> buffer at byte offset bo
    auto prefetch = [&](int jt2, uint32_t bo) {
        int k0b = jt2 * 64;
#pragma unroll
        for (int itr = 0; itr < 2; itr++) {
            int idx = tid + itr * 256;
            int r = idx >> 3, q = idx & 7;
            uint32_t so = (uint32_t)((r * AS + q * 8) * 2);
            size_t gofs = (size_t)(k0b + r) * HD + q * 8;
            CP16(sb + bo + so,          Kh + gofs);
            CP16(sb + bo + 9216 + so,   Kl + gofs);
            CP16(sb + bo + AVHO + so,   Vh + gofs);
            CP16(sb + bo + AVLO + so,   Vl + gofs);
        }
    };

    float m[2] = {-INFINITY, -INFINITY}, lsum[2] = {0.f, 0.f};
    float ov[8][4];
#pragma unroll
    for (int i = 0; i < 8; i++)
#pragma unroll
        for (int c = 0; c < 4; c++) ov[i][c] = 0.f;

    prefetch(0, 0u);
    CPCOMMIT();

    for (int jt = 0; jt < ntiles; jt++) {
        const uint32_t bo = (jt & 1) ? (uint32_t)STG : 0u;
        if (jt + 1 < ntiles) {
            prefetch(jt + 1, ((jt + 1) & 1) ? (uint32_t)STG : 0u);
            CPCOMMIT();
            CPWAIT1();
        } else {
            CPWAIT0();
        }
        __syncthreads();

        const int k0b = jt * 64;
        // S = Q K^T
        float sv[8][4];
#pragma unroll
        for (int i = 0; i < 8; i++)
#pragma unroll
            for (int c = 0; c < 4; c++) sv[i][c] = 0.f;
#pragma unroll
        for (int kt = 0; kt < 4; kt++) {
#pragma unroll
            for (int np = 0; np < 4; np++) {
                uint32_t boff = (uint32_t)(((np * 16 + lr + (g >> 1) * 8) * AS +
                                            kt * 16 + (g & 1) * 8) * 2);
                uint32_t bh[4], bl[4];
                ldm4(sb + bo + boff, bh);
                ldm4(sb + bo + 9216 + boff, bl);
                mma16816(sv[2 * np],     qfh[kt], &bh[0]);
                mma16816(sv[2 * np],     qfh[kt], &bl[0]);
                mma16816(sv[2 * np],     qfl[kt], &bh[0]);
                mma16816(sv[2 * np + 1], qfh[kt], &bh[2]);
                mma16816(sv[2 * np + 1], qfh[kt], &bl[2]);
                mma16816(sv[2 * np + 1], qfl[kt], &bh[2]);
            }
        }

        // scale + causal mask
        const float scale = 0.125f;
        const int rbase = q0 + wid * 16 + (lane >> 2);
        const bool diag = (k0b + 63) > (q0 + wid * 16);
#pragma unroll
        for (int nt = 0; nt < 8; nt++) {
#pragma unroll
            for (int c = 0; c < 4; c++) {
                float s = sv[nt][c] * scale;
                if (diag) {
                    int row = rbase + ((c >> 1) << 3);
                    int col = k0b + nt * 8 + (lane & 3) * 2 + (c & 1);
                    if (col > row) s = -INFINITY;
                }
                sv[nt][c] = s;
            }
        }
        // online softmax
#pragma unroll
        for (int half = 0; half < 2; half++) {
            int ci = half * 2;
            float mt = -INFINITY;
#pragma unroll
            for (int nt = 0; nt < 8; nt++)
                mt = fmaxf(mt, fmaxf(sv[nt][ci], sv[nt][ci + 1]));
            mt = fmaxf(mt, __shfl_xor_sync(0xffffffffu, mt, 1));
            mt = fmaxf(mt, __shfl_xor_sync(0xffffffffu, mt, 2));
            float mn = fmaxf(m[half], mt);
            float corr = __expf(m[half] - mn);
            m[half] = mn;
            float rs = 0.f;
#pragma unroll
            for (int nt = 0; nt < 8; nt++) {
                float p0 = __expf(sv[nt][ci] - mn);
                float p1 = __expf(sv[nt][ci + 1] - mn);
                sv[nt][ci] = p0; sv[nt][ci + 1] = p1;
                rs += p0 + p1;
            }
            rs += __shfl_xor_sync(0xffffffffu, rs, 1);
            rs += __shfl_xor_sync(0xffffffffu, rs, 2);
            lsum[half] = lsum[half] * corr + rs;
#pragma unroll
            for (int dn = 0; dn < 8; dn++) {
                ov[dn][ci] *= corr;
                ov[dn][ci + 1] *= corr;
            }
        }

        // O += P V  (V fragments via ldmatrix.trans on row-major V)
#pragma unroll
        for (int kt = 0; kt < 4; kt++) {
            uint32_t pfh[4], pfl[4];
            hilo2(sv[2 * kt][0],     sv[2 * kt][1],     pfh[0], pfl[0]);
            hilo2(sv[2 * kt][2],     sv[2 * kt][3],     pfh[1], pfl[1]);
            hilo2(sv[2 * kt + 1][0], sv[2 * kt + 1][1], pfh[2], pfl[2]);
            hilo2(sv[2 * kt + 1][2], sv[2 * kt + 1][3], pfh[3], pfl[3]);
#pragma unroll
            for (int dp = 0; dp < 4; dp++) {
                uint32_t vaddr = (uint32_t)(((kt * 16 + (lane & 15)) * AS +
                                             dp * 16 + (lane >> 4) * 8) * 2);
                uint32_t vfh[4], vfl[4];
                ldm4t(sb + bo + AVHO + vaddr, vfh);
                ldm4t(sb + bo + AVLO + vaddr, vfl);
                mma16816(ov[2 * dp],     pfh, &vfh[0]);
                mma16816(ov[2 * dp],     pfh, &vfl[0]);
                mma16816(ov[2 * dp],     pfl, &vfh[0]);
                mma16816(ov[2 * dp + 1], pfh, &vfh[2]);
                mma16816(ov[2 * dp + 1], pfh, &vfl[2]);
                mma16816(ov[2 * dp + 1], pfl, &vfh[2]);
            }
        }
        __syncthreads();
    }

    // epilogue: normalize, split hi/lo, write att [T, 768]
    const int r = lane >> 2, cq = (lane & 3) * 2;
#pragma unroll
    for (int half = 0; half < 2; half++) {
        float inv = 1.f / lsum[half];
        int rg = q0 + wid * 16 + r + half * 8;
#pragma unroll
        for (int dn = 0; dn < 8; dn++) {
            float v0 = ov[dn][half * 2] * inv;
            float v1 = ov[dn][half * 2 + 1] * inv;
            uint32_t hh, ll;
            hilo2(v0, v1, hh, ll);
            size_t base = (size_t)rg * C_EMB + h * HD + dn * 8 + cq;
            *(uint32_t*)(g_ahi + base) = hh;
            *(uint32_t*)(g_alo + base) = ll;
        }
    }
}

// ---------------------------------------------------------------------------
extern "C" void kernel_launch(void* const* d_in, const int* in_sizes, int n_in,
                              void* d_out, int out_size) {
    (void)in_sizes; (void)n_in; (void)out_size;
    const float* x  = (const float*)d_in[0];
    const float* wq = (const float*)d_in[1];
    const float* wk = (const float*)d_in[2];
    const float* wv = (const float*)d_in[3];
    const float* wo = (const float*)d_in[4];
    float* out = (float*)d_out;

    bf16 *xhi, *xlo, *whi, *wlo, *ahi, *alo;
    cudaGetSymbolAddress((void**)&xhi, g_xhi);
    cudaGetSymbolAddress((void**)&xlo, g_xlo);
    cudaGetSymbolAddress((void**)&whi, g_whi);
    cudaGetSymbolAddress((void**)&wlo, g_wlo);
    cudaGetSymbolAddress((void**)&ahi, g_ahi);
    cudaGetSymbolAddress((void**)&alo, g_alo);
    cudaFuncSetAttribute(gemm_tc, cudaFuncAttributeMaxDynamicSharedMemorySize,
                         GEMM_SMEM);
    cudaFuncSetAttribute(attn_tc, cudaFuncAttributeMaxDynamicSharedMemorySize,
                         ATTN_SMEM);
    const size_t WSZ = (size_t)C_EMB * C_EMB;

    int nx4 = (T_SEQ * C_EMB) / 4;
    split_bf16<<<(nx4 + 255) / 256, 256>>>(x, xhi, xlo, nx4);
    split_w4<<<(4 * NW4 + 255) / 256, 256>>>(wq, wk, wv, wo);

    dim3 ggrid(T_SEQ / 128, C_EMB / 128, 3);   // fused QKV: 576 CTAs
    gemm_tc<<<ggrid, 256, GEMM_SMEM>>>(xhi, xlo, whi, wlo, nullptr);

    dim3 agrid(T_SEQ / 128, NH);               // 32 x 12
    attn_tc<<<agrid, 256, ATTN_SMEM>>>();

    dim3 ogrid(T_SEQ / 128, C_EMB / 128, 1);
    gemm_tc<<<ogrid, 256, GEMM_SMEM>>>(ahi, alo, whi + 3 * WSZ, wlo + 3 * WSZ, out);
}

// round 7
// speedup vs baseline: 3.4549x; 1.1829x over previous
#include <cuda_runtime.h>
#include <cuda_bf16.h>
#include <math.h>
#include <stdint.h>

#define T_SEQ 4096
#define C_EMB 768
#define NH    12
#define HD    64
#define NW4   147456          // (768*768)/4

typedef __nv_bfloat16 bf16;
typedef __nv_bfloat162 bf162;

// ---------------------------------------------------------------------------
// Scratch (__device__ globals — allocation-guard-safe)
// ---------------------------------------------------------------------------
__device__ __align__(128) bf16 g_xhi[(size_t)T_SEQ * C_EMB];
__device__ __align__(128) bf16 g_xlo[(size_t)T_SEQ * C_EMB];
__device__ __align__(128) bf16 g_whi[4][(size_t)C_EMB * C_EMB];
__device__ __align__(128) bf16 g_wlo[4][(size_t)C_EMB * C_EMB];
__device__ __align__(128) bf16 g_qhi[(size_t)NH * T_SEQ * HD];
__device__ __align__(128) bf16 g_qlo[(size_t)NH * T_SEQ * HD];
__device__ __align__(128) bf16 g_khi[(size_t)NH * T_SEQ * HD];
__device__ __align__(128) bf16 g_klo[(size_t)NH * T_SEQ * HD];
__device__ __align__(128) bf16 g_vhi[(size_t)NH * T_SEQ * HD];
__device__ __align__(128) bf16 g_vlo[(size_t)NH * T_SEQ * HD];
__device__ __align__(128) bf16 g_ahi[(size_t)T_SEQ * C_EMB];
__device__ __align__(128) bf16 g_alo[(size_t)T_SEQ * C_EMB];

// ---------------------------------------------------------------------------
// Helpers (baseline PTX only — no 'a'-arch features)
// ---------------------------------------------------------------------------
__device__ __forceinline__ uint32_t smem_u32(const void* p) {
    uint32_t a;
    asm("{ .reg .u64 t; cvta.to.shared.u64 t, %1; cvt.u32.u64 %0, t; }"
        : "=r"(a) : "l"(p));
    return a;
}
__device__ __forceinline__ void ldm4(uint32_t addr, uint32_t* r) {
    asm volatile("ldmatrix.sync.aligned.m8n8.x4.shared.b16 {%0,%1,%2,%3}, [%4];"
                 : "=r"(r[0]), "=r"(r[1]), "=r"(r[2]), "=r"(r[3]) : "r"(addr));
}
__device__ __forceinline__ void ldm4t(uint32_t addr, uint32_t* r) {
    asm volatile("ldmatrix.sync.aligned.m8n8.x4.trans.shared.b16 {%0,%1,%2,%3}, [%4];"
                 : "=r"(r[0]), "=r"(r[1]), "=r"(r[2]), "=r"(r[3]) : "r"(addr));
}
__device__ __forceinline__ void mma16816(float* d, const uint32_t* a,
                                         const uint32_t* b) {
    asm volatile(
        "mma.sync.aligned.m16n8k16.row.col.f32.bf16.bf16.f32 "
        "{%0,%1,%2,%3}, {%4,%5,%6,%7}, {%8,%9}, {%0,%1,%2,%3};"
        : "+f"(d[0]), "+f"(d[1]), "+f"(d[2]), "+f"(d[3])
        : "r"(a[0]), "r"(a[1]), "r"(a[2]), "r"(a[3]), "r"(b[0]), "r"(b[1]));
}
__device__ __forceinline__ void hilo2(float v0, float v1, uint32_t& h, uint32_t& l) {
    bf162 hh, ll;
    hh.x = __float2bfloat16(v0); hh.y = __float2bfloat16(v1);
    ll.x = __float2bfloat16(v0 - __bfloat162float(hh.x));
    ll.y = __float2bfloat16(v1 - __bfloat162float(hh.y));
    h = *reinterpret_cast<uint32_t*>(&hh);
    l = *reinterpret_cast<uint32_t*>(&ll);
}
#define CP16(dst, src) \
    asm volatile("cp.async.cg.shared.global [%0], [%1], 16;" \
                 :: "r"(dst), "l"(src) : "memory")
#define CPCOMMIT() asm volatile("cp.async.commit_group;" ::: "memory")
#define CPWAIT0() asm volatile("cp.async.wait_group 0;" ::: "memory")
#define CPWAIT1() asm volatile("cp.async.wait_group 1;" ::: "memory")

// ---------------------------------------------------------------------------
// fp32 -> bf16 (hi, lo) splits
// ---------------------------------------------------------------------------
__global__ __launch_bounds__(256) void split_bf16(const float* __restrict__ src,
                                                  bf16* __restrict__ hi,
                                                  bf16* __restrict__ lo, int n4) {
    int i = blockIdx.x * 256 + threadIdx.x;
    if (i >= n4) return;
    float4 v = ((const float4*)src)[i];
    uint32_t h0, l0, h1, l1;
    hilo2(v.x, v.y, h0, l0);
    hilo2(v.z, v.w, h1, l1);
    ((uint32_t*)hi)[i * 2 + 0] = h0;
    ((uint32_t*)hi)[i * 2 + 1] = h1;
    ((uint32_t*)lo)[i * 2 + 0] = l0;
    ((uint32_t*)lo)[i * 2 + 1] = l1;
}

__global__ __launch_bounds__(256) void split_w4(const float* __restrict__ w0,
                                                const float* __restrict__ w1,
                                                const float* __restrict__ w2,
                                                const float* __restrict__ w3) {
    int i = blockIdx.x * 256 + threadIdx.x;
    if (i >= 4 * NW4) return;
    int m = i / NW4, j = i - m * NW4;
    const float* src = (m == 0) ? w0 : (m == 1) ? w1 : (m == 2) ? w2 : w3;
    float4 v = ((const float4*)src)[j];
    uint32_t h0, l0, h1, l1;
    hilo2(v.x, v.y, h0, l0);
    hilo2(v.z, v.w, h1, l1);
    uint32_t* hp = (uint32_t*)(g_whi[m]);
    uint32_t* lp = (uint32_t*)(g_wlo[m]);
    hp[j * 2 + 0] = h0; hp[j * 2 + 1] = h1;
    lp[j * 2 + 0] = l0; lp[j * 2 + 1] = l1;
}

// ---------------------------------------------------------------------------
// Tensor GEMM: C[t,o] = sum_c X[t,c] * W[o,c], hi/lo split operands.
// CTA 128x128, 8 warps (4m x 2n), k-chunk 64, smem stride 72 bf16.
// __launch_bounds__(256, 2): force 2 CTAs/SM.
// ---------------------------------------------------------------------------
#define GS 72
#define GAH 0
#define GAL 18432
#define GBH 36864
#define GBL 55296
#define GEMM_SMEM 73728

__global__ __launch_bounds__(256, 2) void gemm_tc(
    const bf16* __restrict__ Ahi, const bf16* __restrict__ Alo,
    const bf16* __restrict__ BhiB, const bf16* __restrict__ BloB,
    float* __restrict__ outf) {
    extern __shared__ bf16 smg[];
    const uint32_t sb = smem_u32(smg);
    const int tid = threadIdx.x, lane = tid & 31, wid = tid >> 5;
    const int wm = wid & 3, wn = wid >> 2;
    const int row0 = blockIdx.x * 128, col0 = blockIdx.y * 128;
    const int z = blockIdx.z;
    const bf16* Bhi = BhiB + (size_t)z * C_EMB * C_EMB;
    const bf16* Blo = BloB + (size_t)z * C_EMB * C_EMB;
    const int g = lane >> 3, lr = lane & 7;

    float acc[2][8][4];
#pragma unroll
    for (int i = 0; i < 2; i++)
#pragma unroll
        for (int j = 0; j < 8; j++)
#pragma unroll
            for (int c = 0; c < 4; c++) acc[i][j][c] = 0.f;

    for (int k0 = 0; k0 < C_EMB; k0 += 64) {
#pragma unroll
        for (int itr = 0; itr < 4; itr++) {
            int idx = tid + itr * 256;
            int r = idx >> 3, q = idx & 7;
            size_t ga = (size_t)(row0 + r) * C_EMB + k0 + q * 8;
            size_t gb = (size_t)(col0 + r) * C_EMB + k0 + q * 8;
            uint32_t so = (uint32_t)((r * GS + q * 8) * 2);
            CP16(sb + GAH + so, Ahi + ga);
            CP16(sb + GAL + so, Alo + ga);
            CP16(sb + GBH + so, Bhi + gb);
            CP16(sb + GBL + so, Blo + gb);
        }
        CPCOMMIT();
        CPWAIT0();
        __syncthreads();
#pragma unroll
        for (int kt = 0; kt < 4; kt++) {
            uint32_t ah[2][4], al[2][4];
#pragma unroll
            for (int mt = 0; mt < 2; mt++) {
                int m0 = wm * 32 + mt * 16;
                uint32_t aoff = (uint32_t)(((m0 + lr + (g & 1) * 8) * GS +
                                            kt * 16 + (g >> 1) * 8) * 2);
                ldm4(sb + GAH + aoff, ah[mt]);
                ldm4(sb + GAL + aoff, al[mt]);
            }
#pragma unroll
            for (int np = 0; np < 4; np++) {
                int n0 = wn * 64 + np * 16;
                uint32_t boff = (uint32_t)(((n0 + lr + (g >> 1) * 8) * GS +
                                            kt * 16 + (g & 1) * 8) * 2);
                uint32_t bh[4], bl[4];
                ldm4(sb + GBH + boff, bh);
                ldm4(sb + GBL + boff, bl);
#pragma unroll
                for (int mt = 0; mt < 2; mt++) {
                    mma16816(acc[mt][2 * np],     ah[mt], &bh[0]);
                    mma16816(acc[mt][2 * np],     ah[mt], &bl[0]);
                    mma16816(acc[mt][2 * np],     al[mt], &bh[0]);
                    mma16816(acc[mt][2 * np + 1], ah[mt], &bh[2]);
                    mma16816(acc[mt][2 * np + 1], ah[mt], &bl[2]);
                    mma16816(acc[mt][2 * np + 1], al[mt], &bh[2]);
                }
            }
        }
        __syncthreads();
    }

    const int r = lane >> 2, cq = (lane & 3) * 2;
    bf16* Dhi = (z == 0) ? g_qhi : (z == 1) ? g_khi : g_vhi;
    bf16* Dlo = (z == 0) ? g_qlo : (z == 1) ? g_klo : g_vlo;
#pragma unroll
    for (int mt = 0; mt < 2; mt++) {
#pragma unroll
        for (int nt = 0; nt < 8; nt++) {
            int grow = row0 + wm * 32 + mt * 16 + r;
            int gc = col0 + wn * 64 + nt * 8 + cq;
            if (outf) {
                *(float2*)(outf + (size_t)grow * C_EMB + gc) =
                    make_float2(acc[mt][nt][0], acc[mt][nt][1]);
                *(float2*)(outf + (size_t)(grow + 8) * C_EMB + gc) =
                    make_float2(acc[mt][nt][2], acc[mt][nt][3]);
            } else {
                uint32_t h0, l0, h1, l1;
                hilo2(acc[mt][nt][0], acc[mt][nt][1], h0, l0);
                hilo2(acc[mt][nt][2], acc[mt][nt][3], h1, l1);
                int hh = gc >> 6, d = gc & 63;
                size_t b0 = ((size_t)hh * T_SEQ + grow) * HD + d;
                size_t b1 = ((size_t)hh * T_SEQ + grow + 8) * HD + d;
                *(uint32_t*)(Dhi + b0) = h0;
                *(uint32_t*)(Dlo + b0) = l0;
                *(uint32_t*)(Dhi + b1) = h1;
                *(uint32_t*)(Dlo + b1) = l1;
            }
        }
    }
}

// ---------------------------------------------------------------------------
// Tensor flash attention, causal. BLOCK_M=128 (8 warps x m16), BLOCK_N=64.
// Double-buffered cp.async KV pipeline; Q in its OWN smem region, fragments
// re-loaded via ldmatrix per k-step (frees 32 regs -> 2 CTAs/SM).
// stage layout (bytes): KH=+0 KL=+9216 VH=+18432 VL=+27648 (stage = 36864)
// stage0 @ 0, stage1 @ 36864, QH @ 73728, QL @ 92160. Total 110592 B.
// ---------------------------------------------------------------------------
#define AS  72
#define STG 36864
#define AVHO 18432
#define AVLO 27648
#define AQH 73728
#define AQL 92160
#define ATTN_SMEM 110592

__global__ __launch_bounds__(256, 2) void attn_tc() {
    extern __shared__ char smc[];
    const uint32_t sb = smem_u32(smc);
    const int tid = threadIdx.x, lane = tid & 31, wid = tid >> 5;
    const int g = lane >> 3, lr = lane & 7;
    const int itc = gridDim.x - 1 - blockIdx.x;   // heavy first
    const int h = blockIdx.y;
    const int q0 = itc * 128;
    const int ntiles = 2 * itc + 2;               // KV tiles of 64

    const bf16* Qh = g_qhi + (size_t)h * T_SEQ * HD;
    const bf16* Ql = g_qlo + (size_t)h * T_SEQ * HD;
    const bf16* Kh = g_khi + (size_t)h * T_SEQ * HD;
    const bf16* Kl = g_klo + (size_t)h * T_SEQ * HD;
    const bf16* Vh = g_vhi + (size_t)h * T_SEQ * HD;
    const bf16* Vl = g_vlo + (size_t)h * T_SEQ * HD;

    // Q tile -> dedicated smem region (via cp.async, joins first commit group)
#pragma unroll
    for (int itr = 0; itr < 4; itr++) {
        int idx = tid + itr * 256;
        int r = idx >> 3, q = idx & 7;
        uint32_t so = (uint32_t)((r * AS + q * 8) * 2);
        size_t gofs = (size_t)(q0 + r) * HD + q * 8;
        CP16(sb + AQH + so, Qh + gofs);
        CP16(sb + AQL + so, Ql + gofs);
    }

    // prefetch KV tile jt2 -> buffer at byte offset bo
    auto prefetch = [&](int jt2, uint32_t bo) {
        int k0b = jt2 * 64;
#pragma unroll
        for (int itr = 0; itr < 2; itr++) {
            int idx = tid + itr * 256;
            int r = idx >> 3, q = idx & 7;
            uint32_t so = (uint32_t)((r * AS + q * 8) * 2);
            size_t gofs = (size_t)(k0b + r) * HD + q * 8;
            CP16(sb + bo + so,          Kh + gofs);
            CP16(sb + bo + 9216 + so,   Kl + gofs);
            CP16(sb + bo + AVHO + so,   Vh + gofs);
            CP16(sb + bo + AVLO + so,   Vl + gofs);
        }
    };

    float m[2] = {-INFINITY, -INFINITY}, lsum[2] = {0.f, 0.f};
    float ov[8][4];
#pragma unroll
    for (int i = 0; i < 8; i++)
#pragma unroll
        for (int c = 0; c < 4; c++) ov[i][c] = 0.f;

    prefetch(0, 0u);      // Q + stage0 in group 0
    CPCOMMIT();

    const uint32_t qoff_base = (uint32_t)(((wid * 16 + lr + (g & 1) * 8) * AS +
                                           (g >> 1) * 8) * 2);

    for (int jt = 0; jt < ntiles; jt++) {
        const uint32_t bo = (jt & 1) ? (uint32_t)STG : 0u;
        if (jt + 1 < ntiles) {
            prefetch(jt + 1, ((jt + 1) & 1) ? (uint32_t)STG : 0u);
            CPCOMMIT();
            CPWAIT1();
        } else {
            CPWAIT0();
        }
        __syncthreads();

        const int k0b = jt * 64;
        // S = Q K^T  (Q frags re-loaded per k-step)
        float sv[8][4];
#pragma unroll
        for (int i = 0; i < 8; i++)
#pragma unroll
            for (int c = 0; c < 4; c++) sv[i][c] = 0.f;
#pragma unroll
        for (int kt = 0; kt < 4; kt++) {
            uint32_t qfh[4], qfl[4];
            uint32_t qa = qoff_base + (uint32_t)(kt * 32);
            ldm4(sb + AQH + qa, qfh);
            ldm4(sb + AQL + qa, qfl);
#pragma unroll
            for (int np = 0; np < 4; np++) {
                uint32_t boff = (uint32_t)(((np * 16 + lr + (g >> 1) * 8) * AS +
                                            kt * 16 + (g & 1) * 8) * 2);
                uint32_t bh[4], bl[4];
                ldm4(sb + bo + boff, bh);
                ldm4(sb + bo + 9216 + boff, bl);
                mma16816(sv[2 * np],     qfh, &bh[0]);
                mma16816(sv[2 * np],     qfh, &bl[0]);
                mma16816(sv[2 * np],     qfl, &bh[0]);
                mma16816(sv[2 * np + 1], qfh, &bh[2]);
                mma16816(sv[2 * np + 1], qfh, &bl[2]);
                mma16816(sv[2 * np + 1], qfl, &bh[2]);
            }
        }

        // scale + causal mask
        const float scale = 0.125f;
        const int rbase = q0 + wid * 16 + (lane >> 2);
        const bool diag = (k0b + 63) > (q0 + wid * 16);
#pragma unroll
        for (int nt = 0; nt < 8; nt++) {
#pragma unroll
            for (int c = 0; c < 4; c++) {
                float s = sv[nt][c] * scale;
                if (diag) {
                    int row = rbase + ((c >> 1) << 3);
                    int col = k0b + nt * 8 + (lane & 3) * 2 + (c & 1);
                    if (col > row) s = -INFINITY;
                }
                sv[nt][c] = s;
            }
        }
        // online softmax
#pragma unroll
        for (int half = 0; half < 2; half++) {
            int ci = half * 2;
            float mt = -INFINITY;
#pragma unroll
            for (int nt = 0; nt < 8; nt++)
                mt = fmaxf(mt, fmaxf(sv[nt][ci], sv[nt][ci + 1]));
            mt = fmaxf(mt, __shfl_xor_sync(0xffffffffu, mt, 1));
            mt = fmaxf(mt, __shfl_xor_sync(0xffffffffu, mt, 2));
            float mn = fmaxf(m[half], mt);
            float corr = __expf(m[half] - mn);
            m[half] = mn;
            float rs = 0.f;
#pragma unroll
            for (int nt = 0; nt < 8; nt++) {
                float p0 = __expf(sv[nt][ci] - mn);
                float p1 = __expf(sv[nt][ci + 1] - mn);
                sv[nt][ci] = p0; sv[nt][ci + 1] = p1;
                rs += p0 + p1;
            }
            rs += __shfl_xor_sync(0xffffffffu, rs, 1);
            rs += __shfl_xor_sync(0xffffffffu, rs, 2);
            lsum[half] = lsum[half] * corr + rs;
#pragma unroll
            for (int dn = 0; dn < 8; dn++) {
                ov[dn][ci] *= corr;
                ov[dn][ci + 1] *= corr;
            }
        }

        // O += P V  (V fragments via ldmatrix.trans on row-major V)
#pragma unroll
        for (int kt = 0; kt < 4; kt++) {
            uint32_t pfh[4], pfl[4];
            hilo2(sv[2 * kt][0],     sv[2 * kt][1],     pfh[0], pfl[0]);
            hilo2(sv[2 * kt][2],     sv[2 * kt][3],     pfh[1], pfl[1]);
            hilo2(sv[2 * kt + 1][0], sv[2 * kt + 1][1], pfh[2], pfl[2]);
            hilo2(sv[2 * kt + 1][2], sv[2 * kt + 1][3], pfh[3], pfl[3]);
#pragma unroll
            for (int dp = 0; dp < 4; dp++) {
                uint32_t vaddr = (uint32_t)(((kt * 16 + (lane & 15)) * AS +
                                             dp * 16 + (lane >> 4) * 8) * 2);
                uint32_t vfh[4], vfl[4];
                ldm4t(sb + bo + AVHO + vaddr, vfh);
                ldm4t(sb + bo + AVLO + vaddr, vfl);
                mma16816(ov[2 * dp],     pfh, &vfh[0]);
                mma16816(ov[2 * dp],     pfh, &vfl[0]);
                mma16816(ov[2 * dp],     pfl, &vfh[0]);
                mma16816(ov[2 * dp + 1], pfh, &vfh[2]);
                mma16816(ov[2 * dp + 1], pfh, &vfl[2]);
                mma16816(ov[2 * dp + 1], pfl, &vfh[2]);
            }
        }
        __syncthreads();
    }

    // epilogue: normalize, split hi/lo, write att [T, 768]
    const int r = lane >> 2, cq = (lane & 3) * 2;
#pragma unroll
    for (int half = 0; half < 2; half++) {
        float inv = 1.f / lsum[half];
        int rg = q0 + wid * 16 + r + half * 8;
#pragma unroll
        for (int dn = 0; dn < 8; dn++) {
            float v0 = ov[dn][half * 2] * inv;
            float v1 = ov[dn][half * 2 + 1] * inv;
            uint32_t hh, ll;
            hilo2(v0, v1, hh, ll);
            size_t base = (size_t)rg * C_EMB + h * HD + dn * 8 + cq;
            *(uint32_t*)(g_ahi + base) = hh;
            *(uint32_t*)(g_alo + base) = ll;
        }
    }
}

// ---------------------------------------------------------------------------
extern "C" void kernel_launch(void* const* d_in, const int* in_sizes, int n_in,
                              void* d_out, int out_size) {
    (void)in_sizes; (void)n_in; (void)out_size;
    const float* x  = (const float*)d_in[0];
    const float* wq = (const float*)d_in[1];
    const float* wk = (const float*)d_in[2];
    const float* wv = (const float*)d_in[3];
    const float* wo = (const float*)d_in[4];
    float* out = (float*)d_out;

    bf16 *xhi, *xlo, *whi, *wlo, *ahi, *alo;
    cudaGetSymbolAddress((void**)&xhi, g_xhi);
    cudaGetSymbolAddress((void**)&xlo, g_xlo);
    cudaGetSymbolAddress((void**)&whi, g_whi);
    cudaGetSymbolAddress((void**)&wlo, g_wlo);
    cudaGetSymbolAddress((void**)&ahi, g_ahi);
    cudaGetSymbolAddress((void**)&alo, g_alo);
    cudaFuncSetAttribute(gemm_tc, cudaFuncAttributeMaxDynamicSharedMemorySize,
                         GEMM_SMEM);
    cudaFuncSetAttribute(attn_tc, cudaFuncAttributeMaxDynamicSharedMemorySize,
                         ATTN_SMEM);
    const size_t WSZ = (size_t)C_EMB * C_EMB;

    int nx4 = (T_SEQ * C_EMB) / 4;
    split_bf16<<<(nx4 + 255) / 256, 256>>>(x, xhi, xlo, nx4);
    split_w4<<<(4 * NW4 + 255) / 256, 256>>>(wq, wk, wv, wo);

    dim3 ggrid(T_SEQ / 128, C_EMB / 128, 3);   // fused QKV: 576 CTAs
    gemm_tc<<<ggrid, 256, GEMM_SMEM>>>(xhi, xlo, whi, wlo, nullptr);

    dim3 agrid(T_SEQ / 128, NH);               // 32 x 12
    attn_tc<<<agrid, 256, ATTN_SMEM>>>();

    dim3 ogrid(T_SEQ / 128, C_EMB / 128, 1);
    gemm_tc<<<ogrid, 256, GEMM_SMEM>>>(ahi, alo, whi + 3 * WSZ, wlo + 3 * WSZ, out);
}